// round 14
// baseline (speedup 1.0000x reference)
#include <cuda_runtime.h>
#include <stdint.h>

#define MAX_NODES 100352   // >= 100000, multiple of 16
#define MASK_WORDS (MAX_NODES / 32)        // 3136 words = 12.5 KB
#define NCOMP 75           // compact classes: 0 = dead (C6==0), 1..74 alive
#define TAB_BYTES 608      // 75 * 8 rounded to 16
#define EDGE_SMEM (TAB_BYTES + MAX_NODES)  // ~101 KB -> 2 CTAs/SM
#define EDGE_BLOCK 768
#define EDGE_GRID 304      // 2 CTAs x 152 SMs
#define CNT_BLOCK 512
#define CNT_GRID 304

// Scratch (no cudaMalloc allowed)
__device__ int      g_cn[MAX_NODES];
__device__ uint8_t  g_class[MAX_NODES];     // compact class id
__device__ uint32_t g_maskbits[MASK_WORDS]; // bit i = node i is C or N

// Compact class params {R, C6}. 0=dead; 1..5=Z1..5; 6..55=Z8..57; 56..70=Z72..86;
// 71=C_SP2, 72=C_SP3, 73=N_CN2, 74=N_CN3
__constant__ float2 c_cls[NCOMP] = {
    {0.f,0.f},
    {3.6516f,95.99f},{2.1843f,40.67f},{1.2711f,70.21f},{3.3497f,114.51f},
    {2.7079f,152.36f},
    {2.365f,405.57f},{1.5062f,218.45f},{1.8233f,174.81f},{1.3974f,181.7f},
    {3.3515f,263.02f},{3.0102f,228.1f},{3.1629f,359.43f},{3.2554f,3222.12f},
    {2.9539f,2144.49f},{3.0368f,2072.46f},{2.6598f,1357.42f},{4.0877f,1406.65f},
    {4.1275f,1058.36f},{9.7282f,11498.73f},{8.5322f,3361.33f},{7.2344f,2095.91f},
    {5.3605f,1049.31f},{3.718f,966.27f},{3.6408f,1571.36f},{3.4961f,1183.59f},
    {3.5108f,787.76f},{3.0537f,563.93f},{3.0261f,592.91f},{3.1735f,430.82f},
    {3.1773f,812.57f},{3.8357f,4533.53f},{3.1109f,3440.92f},{3.2122f,3859.82f},
    {2.8263f,2729.6f},{2.412f,1864.19f},{1.894f,1175.73f},{11.2061f,32141.18f},
    {6.821f,27655.14f},{7.2367f,2864.2f},{3.901f,3563.45f},{4.0857f,3266.43f},
    {4.045f,3967.23f},{3.4813f,2233.82f},{3.0487f,1393.49f},{2.7795f,1315.09f},
    {2.8673f,1311.47f},{3.3339f,1460.56f},{3.0086f,1662.99f},{3.9919f,8089.97f},
    {3.4209f,6887.05f},{3.5649f,8799.32f},{3.0288f,6136.5f},{2.262f,3757.31f},
    {1.3837f,2561.18f},{12.171f,66580.83f},
    {6.0791f,27593.76f},{5.7661f,15364.65f},{3.6366f,2734.5f},{4.241f,4801.82f},
    {4.1348f,5685.94f},{3.4213f,2786.0f},{3.2486f,2699.79f},{2.9588f,2282.6f},
    {2.9381f,2476.79f},{2.7711f,2988.7f},{2.5816f,2506.63f},{3.785f,8916.84f},
    {3.5381f,8694.22f},{3.6985f,11821.61f},{3.0551f,8410.64f},
    {2.2348f,429.69f},{1.8219f,184.28f},{2.6454f,720.18f},{2.4667f,482.54f}
};

// Z -> compact class id (Z=6/7 handled via cn in node_kernel; dead rows -> 0)
__constant__ uint8_t c_zmap[87] = {
    0, 1,2,3,4,5, 0,0, 6,7,8,9,10,11,12,13,14,15,16,17,18,19,20,21,22,23,24,
    25,26,27,28,29,30,31,32,33,34,35,36,37,38,39,40,41,42,43,44,45,46,47,48,
    49,50,51,52,53,54,55,
    0,0,0,0,0,0,0,0,0,0,0,0,0,0,   // 58..71 dead
    56,57,58,59,60,61,62,63,64,65,66,67,68,69,70
};

// Phase 0: zero output + cn; build bit-packed C/N mask via warp ballot
__global__ void zero_kernel(float* __restrict__ out, const int* __restrict__ Z, int n) {
    int i = blockIdx.x * blockDim.x + threadIdx.x;
    bool cn_flag = false;
    if (i < n) {
        out[i] = 0.0f;
        g_cn[i] = 0;
        int z = Z[i];
        cn_flag = (z == 6 || z == 7);
    }
    uint32_t w = __ballot_sync(0xFFFFFFFFu, cn_flag);
    if ((threadIdx.x & 31) == 0 && (i >> 5) < MASK_WORDS)
        g_maskbits[i >> 5] = w;
}

// Phase 1: coordination count, only for C/N receivers (12.5 KB bitmask in smem)
__global__ void __launch_bounds__(CNT_BLOCK)
count_kernel(const int* __restrict__ recv, int n4, int n) {
    __shared__ uint32_t s_bits[MASK_WORDS];
    for (int j = threadIdx.x; j < MASK_WORDS; j += blockDim.x)
        s_bits[j] = g_maskbits[j];
    __syncthreads();
    const int4* r4 = (const int4*)recv;
    int stride = gridDim.x * blockDim.x;
    for (int i = blockIdx.x * blockDim.x + threadIdx.x; i < n4; i += stride) {
        int4 t = r4[i];
        if ((s_bits[t.x >> 5] >> (t.x & 31)) & 1u) atomicAdd(&g_cn[t.x], 1);
        if ((s_bits[t.y >> 5] >> (t.y & 31)) & 1u) atomicAdd(&g_cn[t.y], 1);
        if ((s_bits[t.z >> 5] >> (t.z & 31)) & 1u) atomicAdd(&g_cn[t.z], 1);
        if ((s_bits[t.w >> 5] >> (t.w & 31)) & 1u) atomicAdd(&g_cn[t.w], 1);
    }
    if (blockIdx.x == 0 && threadIdx.x == 0) {
        for (int j = n4 * 4; j < n; j++) {
            int t = recv[j];
            if ((s_bits[t >> 5] >> (t & 31)) & 1u) atomicAdd(&g_cn[t], 1);
        }
    }
}

__global__ void count_kernel_scalar(const int* __restrict__ recv, int n) {
    int i = blockIdx.x * blockDim.x + threadIdx.x;
    if (i < n) {
        int t = recv[i];
        if ((g_maskbits[t >> 5] >> (t & 31)) & 1u) atomicAdd(&g_cn[t], 1);
    }
}

// Phase 2: assign compact class id per node
__global__ void node_kernel(const int* __restrict__ Z, int n) {
    int i = blockIdx.x * blockDim.x + threadIdx.x;
    if (i < n) {
        int z = Z[i];
        uint8_t c;
        if (z == 6)      c = (g_cn[i] <= 3) ? 71 : 72;
        else if (z == 7) c = (g_cn[i] <= 2) ? 73 : 74;
        else             c = c_zmap[z];
        g_class[i] = c;
    }
}

// smem: [0, TAB_BYTES) per-class float2 {R^(1/4), sqrt(C6)}; then class bytes
__device__ __forceinline__ void edge_smem_setup(char* smem) {
    float2* s_par = (float2*)smem;
    if (threadIdx.x < NCOMP) {
        float2 p = c_cls[threadIdx.x];
        s_par[threadIdx.x] = make_float2(sqrtf(sqrtf(p.x)), sqrtf(p.y));
    }
    const int4* src = (const int4*)g_class;
    int4* dst = (int4*)(smem + TAB_BYTES);
    for (int j = threadIdx.x; j < MAX_NODES / 16; j += blockDim.x) dst[j] = src[j];
    __syncthreads();
}

// Single-divide edge math given gathered params.
__device__ __forceinline__ float edge_math(float px, float c6, float r) {
    float r0 = fmaf(0.4f, px, 4.0f);
    float r2 = r * r, rr4 = r2 * r2, r6 = rr4 * r2, r8 = rr4 * rr4;
    float r14 = r8 * r6;
    float b2 = r0 * r0, b4 = b2 * b2, b8 = b4 * b4;
    float b14 = b8 * b4 * b2;
    float p2 = px * px, p4 = p2 * p2, p8 = p4 * p4;
    float Rij6 = p8 * p4;
    float den = fmaf(6.0f, b14, r14) * (Rij6 + r6);
    float x  = fmaf(0.5f, r, -4.0f);
    float x2 = x * x, x6 = x2 * x2 * x2;
    float env = 1.0f + x6 * (-28.0f + x * (48.0f - 21.0f * x));
    env = (r < 8.0f)  ? 1.0f : env;
    env = (r < 10.0f) ? env  : 0.0f;
    // e_half = 0.5 * C6 * r14/den * env (sign applied at RED)
    return __fdividef(0.5f * c6 * r14, den) * env;
}

// Phase 3: edge energies — software-pipelined global loads, phase-batched gathers
__global__ void __launch_bounds__(EDGE_BLOCK, 2)
edge_kernel(const int* __restrict__ snd, const int* __restrict__ recv,
            const float* __restrict__ len, float* __restrict__ out,
            int n4, int n) {
    extern __shared__ char smem[];
    edge_smem_setup(smem);
    const float2*  s_par = (const float2*)smem;
    const uint8_t* s_cls = (const uint8_t*)(smem + TAB_BYTES);

    const int4*   s4 = (const int4*)snd;
    const int4*   t4 = (const int4*)recv;
    const float4* r4 = (const float4*)len;
    int stride = gridDim.x * blockDim.x;
    int idx = blockIdx.x * blockDim.x + threadIdx.x;

    int4 s, t; float4 r;
    bool valid = (idx < n4);
    if (valid) { s = s4[idx]; t = t4[idx]; r = r4[idx]; }

    while (valid) {
        // prefetch next iteration's streaming loads
        int nidx = idx + stride;
        bool nvalid = (nidx < n4);
        int4 s_n, t_n; float4 r_n;
        if (nvalid) { s_n = s4[nidx]; t_n = t4[nidx]; r_n = r4[nidx]; }

        // phase A: all 8 class-byte gathers (batched -> overlapped LDS latency)
        int cs0 = s_cls[s.x], cs1 = s_cls[s.y], cs2 = s_cls[s.z], cs3 = s_cls[s.w];
        int ct0 = s_cls[t.x], ct1 = s_cls[t.y], ct2 = s_cls[t.z], ct3 = s_cls[t.w];

        // phase B: all 8 param gathers
        float2 a0 = s_par[cs0], a1 = s_par[cs1], a2 = s_par[cs2], a3 = s_par[cs3];
        float2 b0 = s_par[ct0], b1 = s_par[ct1], b2 = s_par[ct2], b3 = s_par[ct3];

        // phase C: math (independent chains x4)
        float e0 = edge_math(a0.x * b0.x, a0.y * b0.y, r.x);
        float e1 = edge_math(a1.x * b1.x, a1.y * b1.y, r.y);
        float e2 = edge_math(a2.x * b2.x, a2.y * b2.y, r.z);
        float e3 = edge_math(a3.x * b3.x, a3.y * b3.y, r.w);

        // phase D: scattered reductions (predicated, no divergence region)
        if (e0 != 0.0f) atomicAdd(&out[t.x], -e0);
        if (e1 != 0.0f) atomicAdd(&out[t.y], -e1);
        if (e2 != 0.0f) atomicAdd(&out[t.z], -e2);
        if (e3 != 0.0f) atomicAdd(&out[t.w], -e3);

        s = s_n; t = t_n; r = r_n;
        idx = nidx; valid = nvalid;
    }

    if (blockIdx.x == 0 && threadIdx.x == 0) {
        for (int j = n4 * 4; j < n; j++) {
            int sj = snd[j], tj = recv[j];
            float2 a = s_par[s_cls[sj]], b = s_par[s_cls[tj]];
            float e = edge_math(a.x * b.x, a.y * b.y, len[j]);
            if (e != 0.0f) atomicAdd(&out[tj], -e);
        }
    }
}

// Scalar fallback (misaligned edge halves)
__global__ void __launch_bounds__(EDGE_BLOCK, 2)
edge_kernel_scalar(const int* __restrict__ snd, const int* __restrict__ recv,
                   const float* __restrict__ len, float* __restrict__ out, int n) {
    extern __shared__ char smem[];
    edge_smem_setup(smem);
    const float2*  s_par = (const float2*)smem;
    const uint8_t* s_cls = (const uint8_t*)(smem + TAB_BYTES);
    int stride = gridDim.x * blockDim.x;
    for (int i = blockIdx.x * blockDim.x + threadIdx.x; i < n; i += stride) {
        int sj = snd[i], tj = recv[i];
        float2 a = s_par[s_cls[sj]], b = s_par[s_cls[tj]];
        float e = edge_math(a.x * b.x, a.y * b.y, len[i]);
        if (e != 0.0f) atomicAdd(&out[tj], -e);
    }
}

extern "C" void kernel_launch(void* const* d_in, const int* in_sizes, int n_in,
                              void* d_out, int out_size) {
    const int*   Z   = (const int*)d_in[0];
    const int*   ei  = (const int*)d_in[1];
    const float* len = (const float*)d_in[2];
    float* out = (float*)d_out;

    int n_nodes = in_sizes[0];
    int n_edges = in_sizes[2];
    const int* snd  = ei;
    const int* recv = ei + n_edges;

    static bool attr_done = false;
    if (!attr_done) {
        cudaFuncSetAttribute(edge_kernel,
            cudaFuncAttributeMaxDynamicSharedMemorySize, EDGE_SMEM);
        cudaFuncSetAttribute(edge_kernel_scalar,
            cudaFuncAttributeMaxDynamicSharedMemorySize, EDGE_SMEM);
        attr_done = true;
    }

    const int TB = 256;
    zero_kernel<<<(MAX_NODES + TB - 1) / TB, TB>>>(out, Z, n_nodes);

    bool vec_ok = ((n_edges & 3) == 0);
    if (vec_ok) {
        int n4 = n_edges >> 2;
        count_kernel<<<CNT_GRID, CNT_BLOCK>>>(recv, n4, n_edges);
        node_kernel<<<(n_nodes + TB - 1) / TB, TB>>>(Z, n_nodes);
        edge_kernel<<<EDGE_GRID, EDGE_BLOCK, EDGE_SMEM>>>(snd, recv, len, out, n4, n_edges);
    } else {
        count_kernel_scalar<<<(n_edges + TB - 1) / TB, TB>>>(recv, n_edges);
        node_kernel<<<(n_nodes + TB - 1) / TB, TB>>>(Z, n_nodes);
        edge_kernel_scalar<<<EDGE_GRID, EDGE_BLOCK, EDGE_SMEM>>>(snd, recv, len, out, n_edges);
    }
}